// round 8
// baseline (speedup 1.0000x reference)
#include <cuda_runtime.h>
#include <cuda_fp16.h>
#include <cstdint>

#define NA 512
#define NB 512
#define ND 128
#define ED 128

#define PADB 144
#define TILEB 18432        // 128 * 144

// ---------------- device scratch ----------------
__device__ float g_A1[NA * ED];
__device__ float g_B1[NB * ED];
__device__ unsigned long long g_sumA_i64[NA * ED];
__device__ unsigned long long g_sumB_i64[NB * ED];
__device__ __align__(16) char g_WeB[4 * 2 * TILEB];    // We^T  4 chunks: [hi|lo] fp16
__device__ __align__(16) char g_We2B[2 * 2 * TILEB];   // We2^T 2 chunks: [hi|lo] fp16

#define SUM_SCALE 4294967296.0f
#define SUM_INV   2.3283064365386963e-10f

// ---------------- helpers ----------------
__device__ __forceinline__ uint32_t smem_u32(const void* p) {
    uint32_t a;
    asm("{ .reg .u64 t; cvta.to.shared.u64 t, %1; cvt.u32.u64 %0, t; }" : "=r"(a) : "l"(p));
    return a;
}
__device__ __forceinline__ uint32_t cvt2h(float f0, float f1) {
    uint32_t r;
    asm("cvt.rn.f16x2.f32 %0, %1, %2;" : "=r"(r) : "f"(f1), "f"(f0));  // low half = f0
    return r;
}
__device__ __forceinline__ void mma16816(float* c, const uint32_t* a, uint32_t b0, uint32_t b1) {
    asm volatile(
        "mma.sync.aligned.m16n8k16.row.col.f32.f16.f16.f32 "
        "{%0,%1,%2,%3}, {%4,%5,%6,%7}, {%8,%9}, {%0,%1,%2,%3};"
        : "+f"(c[0]), "+f"(c[1]), "+f"(c[2]), "+f"(c[3])
        : "r"(a[0]), "r"(a[1]), "r"(a[2]), "r"(a[3]), "r"(b0), "r"(b1));
}
__device__ __forceinline__ void ldsm4(uint32_t* r, uint32_t addr) {
    asm volatile("ldmatrix.sync.aligned.m8n8.x4.shared.b16 {%0,%1,%2,%3}, [%4];"
                 : "=r"(r[0]), "=r"(r[1]), "=r"(r[2]), "=r"(r[3]) : "r"(addr));
}
#define CP16(dst, src) asm volatile("cp.async.cg.shared.global [%0], [%1], 16;" :: "r"(dst), "l"(src))
#define CP_COMMIT()    asm volatile("cp.async.commit_group;" ::: "memory")
#define CP_WAIT(n)     asm volatile("cp.async.wait_group %0;" :: "n"(n) : "memory")

// ---------------- SMEM layout (bytes) ----------------
#define ABUF    0                       // TILEB = 18432 : A fp16; then h chunk0
#define BBUF    18432                   // 2 stages x 2*TILEB = 73728 ; stage0 reused for h chunk1
#define WE2     92160                   // 4*TILEB = 73728 : {hi0|lo0|hi1|lo1}
#define SM_A1   165888                  // 8*132*4  = 4224
#define SM_B1   170112                  // 16*132*4 = 8448
#define SM_BE2  178560                  // 512
#define SM_TOTAL 179072
// sL overlay at ABUF: 128*132*4 = 67584 bytes (fits in ABUF+BBUF span = 92160)

// ---------------------------------------------------------------------------
// k_prep: node pre-GEMMs + fp16 hi/lo weight images + zero sum buffers.
// grid 168 x 256.
// ---------------------------------------------------------------------------
__global__ void k_prep(const float* __restrict__ na, const float* __restrict__ nb,
                       const float* __restrict__ We1, const float* __restrict__ be1,
                       const float* __restrict__ We2w) {
    int blk = blockIdx.x, t = threadIdx.x;
    if (blk < 128) {
        bool isA = blk < 64;
        int r0 = (isA ? blk : blk - 64) * 8;
        const float* X = isA ? na : nb;
        const float* W = We1 + (isA ? 0 : ND) * ED;
        __shared__ float xs[8][ND];
        for (int i = t; i < 8 * ND; i += 256) xs[i >> 7][i & 127] = X[(r0 + (i >> 7)) * ND + (i & 127)];
        __syncthreads();
        if (t < 128) {
            int d = t;
            float acc[8];
            float bb = isA ? be1[d] : 0.0f;
#pragma unroll
            for (int i = 0; i < 8; i++) acc[i] = bb;
#pragma unroll 4
            for (int k = 0; k < ND; k++) {
                float w = W[k * ED + d];
#pragma unroll
                for (int i = 0; i < 8; i++) acc[i] = fmaf(xs[i][k], w, acc[i]);
            }
            float* dst = isA ? g_A1 : g_B1;
#pragma unroll
            for (int i = 0; i < 8; i++) dst[(r0 + i) * ED + d] = acc[i];
        }
    } else if (blk < 152) {
        // fp16 hi/lo weight images; thread handles 8 consecutive k (j) for one n.
        int wu = (blk - 128) * 256 + t;        // 0..6143
        int region = wu >> 10;                  // 0..5
        int r = wu & 1023;
        int n = r >> 3;
        int jj = (r & 7) * 8;
        const float* src;
        char* base;
        if (region < 4) {
            src = We1 + (size_t)(2 * ND + region * 64 + jj) * ED + n;
            base = g_WeB + region * 2 * TILEB;
        } else {
            int c = region - 4;
            src = We2w + (size_t)(c * 64 + jj) * ED + n;
            base = g_We2B + c * 2 * TILEB;
        }
        float x[8];
#pragma unroll
        for (int s2 = 0; s2 < 8; s2++) x[s2] = __ldg(src + (size_t)s2 * ED);
        uint32_t hw[4], lw[4];
#pragma unroll
        for (int p = 0; p < 4; p++) {
            uint32_t hp = cvt2h(x[2 * p], x[2 * p + 1]);
            __half2 hh = *(__half2*)&hp;
            float l0 = x[2 * p]     - __low2float(hh);
            float l1 = x[2 * p + 1] - __high2float(hh);
            hw[p] = hp;
            lw[p] = cvt2h(l0, l1);
        }
        *(uint4*)(base + n * PADB + jj * 2)         = make_uint4(hw[0], hw[1], hw[2], hw[3]);
        *(uint4*)(base + TILEB + n * PADB + jj * 2) = make_uint4(lw[0], lw[1], lw[2], lw[3]);
    } else {
        // zero the int64 sum accumulators (1 MB total)
        int zi = (blk - 152) * 256 + t;        // 0..4095
        uint4 z = make_uint4(0, 0, 0, 0);
#pragma unroll
        for (int k = 0; k < 16; k++) {
            int idx = zi + k * 4096;           // 0..65535 uint4
            if (idx < 32768) ((uint4*)g_sumA_i64)[idx] = z;
            else             ((uint4*)g_sumB_i64)[idx - 32768] = z;
        }
    }
}

// ---------------------------------------------------------------------------
// E-chunk prefetch (LDG->regs) and fp16 store (regs->smem, single image)
// ---------------------------------------------------------------------------
__device__ __forceinline__ void ldgA(float4* pf, const float* __restrict__ E,
                                     int a0, int b0, int c, int t) {
#pragma unroll
    for (int it = 0; it < 4; it++) {
        int u = t + it * 256;
        int m = u >> 3, g = u & 7;
        int a = a0 + (m >> 4), b = b0 + (m & 15);
        const float4* src = (const float4*)(E + (((size_t)(a * NB + b)) << 8) + c * 64 + g * 8);
        pf[it * 2]     = __ldg(src);
        pf[it * 2 + 1] = __ldg(src + 1);
    }
}
__device__ __forceinline__ void stsA(const float4* pf, char* A, int t) {
#pragma unroll
    for (int it = 0; it < 4; it++) {
        int u = t + it * 256;
        int m = u >> 3, g = u & 7;
        float4 v0 = pf[it * 2], v1 = pf[it * 2 + 1];
        uint32_t w0 = cvt2h(v0.x, v0.y), w1 = cvt2h(v0.z, v0.w);
        uint32_t w2 = cvt2h(v1.x, v1.y), w3 = cvt2h(v1.z, v1.w);
        *(uint4*)(A + m * PADB + g * 16) = make_uint4(w0, w1, w2, w3);
    }
}

// ---------------------------------------------------------------------------
// one 64-k chunk: A single fp16, B = hi + lo  (2 MMAs per atom)
// ---------------------------------------------------------------------------
__device__ __forceinline__ void gemm_chunk(uint32_t aA, uint32_t aBh, uint32_t aBl,
                                           float acc[2][8][4]) {
#pragma unroll
    for (int kk = 0; kk < 4; kk++) {
        uint32_t a0v[4], a1v[4];
        ldsm4(a0v, aA + kk * 32);
        ldsm4(a1v, aA + 16 * PADB + kk * 32);
#pragma unroll
        for (int jp = 0; jp < 4; jp++) {
            uint32_t bh[4], bl[4];
            ldsm4(bh, aBh + jp * 16 * PADB + kk * 32);
            ldsm4(bl, aBl + jp * 16 * PADB + kk * 32);
            mma16816(acc[0][2 * jp],     a0v, bh[0], bh[1]);
            mma16816(acc[0][2 * jp],     a0v, bl[0], bl[1]);
            mma16816(acc[0][2 * jp + 1], a0v, bh[2], bh[3]);
            mma16816(acc[0][2 * jp + 1], a0v, bl[2], bl[3]);
            mma16816(acc[1][2 * jp],     a1v, bh[0], bh[1]);
            mma16816(acc[1][2 * jp],     a1v, bl[0], bl[1]);
            mma16816(acc[1][2 * jp + 1], a1v, bh[2], bh[3]);
            mma16816(acc[1][2 * jp + 1], a1v, bl[2], bl[3]);
        }
    }
}

// ---------------------------------------------------------------------------
// k_edge
// ---------------------------------------------------------------------------
__global__ __launch_bounds__(256, 1)
void k_edge(const float* __restrict__ E, const float* __restrict__ be2,
            float* __restrict__ out) {
    extern __shared__ char sm[];
    const int t = threadIdx.x, lane = t & 31, wid = t >> 5;
    const int wm = wid >> 1, wn = wid & 1;
    const int lr = lane >> 2, lc = lane & 3;
    const int bt = blockIdx.x, at = blockIdx.y;
    const int b0 = bt * 16, a0 = at * 8;

    float* sA1 = (float*)(sm + SM_A1);
    float* sB1 = (float*)(sm + SM_B1);
    float* sbe2 = (float*)(sm + SM_BE2);
    const uint32_t smb = smem_u32(sm);

    const uint32_t aoff = (uint32_t)((wm * 32 + (lane & 15)) * PADB + (lane >> 4) * 16);
    const uint32_t boff = (uint32_t)((wn * 64 + (lane & 7) + ((lane >> 4) << 3)) * PADB
                                     + ((lane >> 3) & 1) * 16);

    // ---- prologue ----
    for (int i = t; i < 2304; i += 256)
        CP16(smb + BBUF + i * 16, g_WeB + i * 16);
    CP_COMMIT();
    for (int i = t; i < 4608; i += 256)
        CP16(smb + WE2 + i * 16, g_We2B + i * 16);
    CP_COMMIT();

    float4 pf[8];
    ldgA(pf, E, a0, b0, 0, t);
    stsA(pf, sm + ABUF, t);

    for (int i = t; i < 8 * ED; i += 256)  sA1[(i >> 7) * 132 + (i & 127)] = g_A1[(a0 + (i >> 7)) * ED + (i & 127)];
    for (int i = t; i < 16 * ED; i += 256) sB1[(i >> 7) * 132 + (i & 127)] = g_B1[(b0 + (i >> 7)) * ED + (i & 127)];
    if (t < 128) sbe2[t] = be2[t];

    CP_WAIT(1);
    __syncthreads();

    float acc[2][8][4];
#pragma unroll
    for (int i = 0; i < 2; i++)
#pragma unroll
        for (int j = 0; j < 8; j++)
#pragma unroll
            for (int q = 0; q < 4; q++) acc[i][j][q] = 0.0f;

    // ---- GEMM1: 4 k-chunks ----
#pragma unroll
    for (int c = 0; c < 4; c++) {
        int s = c & 1;
        if (c < 3) {
            ldgA(pf, E, a0, b0, c + 1, t);
            uint32_t dst = smb + BBUF + (s ^ 1) * 2 * TILEB;
            const char* src = g_WeB + (c + 1) * 2 * TILEB;
            for (int i = t; i < 2304; i += 256)
                CP16(dst + i * 16, src + i * 16);
            CP_COMMIT();
        }
        uint32_t bb = smb + BBUF + s * 2 * TILEB;
        gemm_chunk(smb + ABUF + aoff, bb + boff, bb + TILEB + boff, acc);
        __syncthreads();
        if (c < 3) {
            stsA(pf, sm + ABUF, t);
            CP_WAIT(0);
            __syncthreads();
        }
    }

    // ---- epilogue 1: h = relu(D + A1 + B1) -> fp16 image (chunk0=ABUF, chunk1=BBUF) ----
    {
        char* Hh = (wn == 0) ? (sm + ABUF) : (sm + BBUF);
#pragma unroll
        for (int i = 0; i < 2; i++) {
#pragma unroll
            for (int j = 0; j < 8; j++) {
                int m0 = wm * 32 + i * 16 + lr;
                int col = wn * 64 + j * 8 + lc * 2;
                int cc2 = (col & 63) * 2;
                float f0 = fmaxf(acc[i][j][0] + sA1[(m0 >> 4) * 132 + col]     + sB1[(m0 & 15) * 132 + col],     0.0f);
                float f1 = fmaxf(acc[i][j][1] + sA1[(m0 >> 4) * 132 + col + 1] + sB1[(m0 & 15) * 132 + col + 1], 0.0f);
                *(uint32_t*)(Hh + m0 * PADB + cc2) = cvt2h(f0, f1);
                int m1 = m0 + 8;
                f0 = fmaxf(acc[i][j][2] + sA1[(m1 >> 4) * 132 + col]     + sB1[(m1 & 15) * 132 + col],     0.0f);
                f1 = fmaxf(acc[i][j][3] + sA1[(m1 >> 4) * 132 + col + 1] + sB1[(m1 & 15) * 132 + col + 1], 0.0f);
                *(uint32_t*)(Hh + m1 * PADB + cc2) = cvt2h(f0, f1);
            }
        }
    }
    __syncthreads();

    // ---- GEMM2: h @ We2, 2 k-chunks ----
#pragma unroll
    for (int i = 0; i < 2; i++)
#pragma unroll
        for (int j = 0; j < 8; j++)
#pragma unroll
            for (int q = 0; q < 4; q++) acc[i][j][q] = 0.0f;

#pragma unroll
    for (int c2 = 0; c2 < 2; c2++) {
        uint32_t ha = smb + ((c2 == 0) ? ABUF : BBUF);
        uint32_t wb = smb + WE2 + c2 * 2 * TILEB;
        gemm_chunk(ha + aoff, wb + boff, wb + TILEB + boff, acc);
    }
    __syncthreads();

    // ---- epilogue 2: L = relu(D + be2) -> sL ----
    float* sL = (float*)(sm + ABUF);
#pragma unroll
    for (int i = 0; i < 2; i++) {
#pragma unroll
        for (int j = 0; j < 8; j++) {
            int m0 = wm * 32 + i * 16 + lr;
            int col = wn * 64 + j * 8 + lc * 2;
            sL[m0 * 132 + col]     = fmaxf(acc[i][j][0] + sbe2[col],     0.0f);
            sL[m0 * 132 + col + 1] = fmaxf(acc[i][j][1] + sbe2[col + 1], 0.0f);
            int m1 = m0 + 8;
            sL[m1 * 132 + col]     = fmaxf(acc[i][j][2] + sbe2[col],     0.0f);
            sL[m1 * 132 + col + 1] = fmaxf(acc[i][j][3] + sbe2[col + 1], 0.0f);
        }
    }
    __syncthreads();

    // ---- coalesced out writes ----
    for (int i = t; i < 4096; i += 256) {
        int m = i >> 5;
        int cg = (i & 31) * 4;
        int ga = a0 + (m >> 4), gb = b0 + (m & 15);
        *(float4*)&out[((size_t)(ga * NB + gb)) * ED + cg] = *(float4*)&sL[m * 132 + cg];
    }

    // ---- deterministic scaled-int64 reductions ----
    for (int q = t; q < 8 * ED; q += 256) {
        int la2 = q >> 7, n = q & 127;
        long long s = 0;
#pragma unroll
        for (int lb2 = 0; lb2 < 16; lb2++)
            s += llrintf(sL[(la2 * 16 + lb2) * 132 + n] * SUM_SCALE);
        atomicAdd(&g_sumA_i64[(a0 + la2) * ED + n], (unsigned long long)s);
    }
    for (int q = t; q < 16 * ED; q += 256) {
        int lb2 = q >> 7, n = q & 127;
        long long s = 0;
#pragma unroll
        for (int la2 = 0; la2 < 8; la2++)
            s += llrintf(sL[(la2 * 16 + lb2) * 132 + n] * SUM_SCALE);
        atomicAdd(&g_sumB_i64[(b0 + lb2) * ED + n], (unsigned long long)s);
    }
}

// ---------------------------------------------------------------------------
// k_node: read exact int64 sums + node MLPs.
// ---------------------------------------------------------------------------
__global__ void k_node(const float* __restrict__ na, const float* __restrict__ nb,
                       const float* __restrict__ Wn1, const float* __restrict__ bn1,
                       const float* __restrict__ Wn2, const float* __restrict__ bn2,
                       float* __restrict__ out) {
    int r = blockIdx.x;
    int d = threadIdx.x;
    bool isA = (r < NA);
    int rr = isA ? r : r - NA;
    __shared__ float xs[2 * ND];
    __shared__ float h1[ND];
    xs[d] = (isA ? na : nb)[rr * ND + d];
    long long v = (long long)(isA ? g_sumA_i64[rr * ED + d] : g_sumB_i64[rr * ED + d]);
    xs[ND + d] = (float)v * SUM_INV;
    __syncthreads();
    float acc = bn1[d];
#pragma unroll 8
    for (int k = 0; k < 2 * ND; k++) acc = fmaf(xs[k], Wn1[k * ND + d], acc);
    h1[d] = fmaxf(acc, 0.0f);
    __syncthreads();
    float acc2 = bn2[d];
#pragma unroll 8
    for (int k = 0; k < ND; k++) acc2 = fmaf(h1[k], Wn2[k * ND + d], acc2);
    size_t off = (size_t)NA * NB * ED + (isA ? 0 : (size_t)NA * ND) + (size_t)rr * ND + d;
    out[off] = fmaxf(acc2, 0.0f);
}

// ---------------------------------------------------------------------------
extern "C" void kernel_launch(void* const* d_in, const int* in_sizes, int n_in,
                              void* d_out, int out_size) {
    const float* edge = (const float*)d_in[0];
    const float* na   = (const float*)d_in[1];
    const float* nb   = (const float*)d_in[2];
    const float* We1  = (const float*)d_in[3];
    const float* be1  = (const float*)d_in[4];
    const float* We2  = (const float*)d_in[5];
    const float* be2  = (const float*)d_in[6];
    const float* Wn1  = (const float*)d_in[7];
    const float* bn1  = (const float*)d_in[8];
    const float* Wn2  = (const float*)d_in[9];
    const float* bn2  = (const float*)d_in[10];
    float* out = (float*)d_out;

    k_prep<<<168, 256>>>(na, nb, We1, be1, We2);

    static int smem_set = 0;
    if (!smem_set) {
        cudaFuncSetAttribute(k_edge, cudaFuncAttributeMaxDynamicSharedMemorySize, SM_TOTAL);
        smem_set = 1;
    }
    dim3 grid(NB / 16, NA / 8);
    k_edge<<<grid, 256, SM_TOTAL>>>(edge, be2, out);

    k_node<<<NA + NB, 128>>>(na, nb, Wn1, bn1, Wn2, bn2, out);
}

// round 9
// speedup vs baseline: 1.3247x; 1.3247x over previous
#include <cuda_runtime.h>
#include <cuda_fp16.h>
#include <cstdint>

#define NA 512
#define NB 512
#define ND 128
#define ED 128

#define PADB 144
#define TILEB 18432        // 128 * 144

// ---------------- device scratch ----------------
__device__ float g_A1[NA * ED];
__device__ float g_B1[NB * ED];
__device__ float g_sumA_part[(size_t)NA * 32 * ED];   // [a][b_tile(32)][d]
__device__ float g_sumB_part[(size_t)NB * 64 * ED];   // [b][a_tile(64)][d]
__device__ __align__(16) char g_WeB[4 * 2 * TILEB];    // We^T  4 chunks: [hi|lo] fp16
__device__ __align__(16) char g_We2B[2 * 2 * TILEB];   // We2^T 2 chunks: [hi|lo] fp16

// ---------------- helpers ----------------
__device__ __forceinline__ uint32_t smem_u32(const void* p) {
    uint32_t a;
    asm("{ .reg .u64 t; cvta.to.shared.u64 t, %1; cvt.u32.u64 %0, t; }" : "=r"(a) : "l"(p));
    return a;
}
__device__ __forceinline__ uint32_t cvt2h(float f0, float f1) {
    uint32_t r;
    asm("cvt.rn.f16x2.f32 %0, %1, %2;" : "=r"(r) : "f"(f1), "f"(f0));  // low half = f0
    return r;
}
__device__ __forceinline__ void mma16816(float* c, const uint32_t* a, uint32_t b0, uint32_t b1) {
    asm volatile(
        "mma.sync.aligned.m16n8k16.row.col.f32.f16.f16.f32 "
        "{%0,%1,%2,%3}, {%4,%5,%6,%7}, {%8,%9}, {%0,%1,%2,%3};"
        : "+f"(c[0]), "+f"(c[1]), "+f"(c[2]), "+f"(c[3])
        : "r"(a[0]), "r"(a[1]), "r"(a[2]), "r"(a[3]), "r"(b0), "r"(b1));
}
__device__ __forceinline__ void ldsm4(uint32_t* r, uint32_t addr) {
    asm volatile("ldmatrix.sync.aligned.m8n8.x4.shared.b16 {%0,%1,%2,%3}, [%4];"
                 : "=r"(r[0]), "=r"(r[1]), "=r"(r[2]), "=r"(r[3]) : "r"(addr));
}
#define CP16(dst, src) asm volatile("cp.async.cg.shared.global [%0], [%1], 16;" :: "r"(dst), "l"(src))
#define CP_COMMIT()    asm volatile("cp.async.commit_group;" ::: "memory")
#define CP_WAIT(n)     asm volatile("cp.async.wait_group %0;" :: "n"(n) : "memory")

// ---------------- SMEM layout (bytes) ----------------
#define ABUF    0                       // TILEB : A fp16; then h chunk0
#define BBUF    18432                   // 2 stages x 2*TILEB = 73728 ; stage0 reused for h chunk1
#define WE2     92160                   // 4*TILEB = 73728 : {hi0|lo0|hi1|lo1}
#define SM_A1   165888                  // 8*132*4  = 4224
#define SM_B1   170112                  // 16*132*4 = 8448
#define SM_BE2  178560                  // 512
#define SM_TOTAL 179072
// sL overlay at ABUF: 128*132*4 = 67584 bytes (fits in ABUF..BBUF span = 92160)

// ---------------------------------------------------------------------------
// k_prep: node pre-GEMMs + fp16 hi/lo weight images. grid 152 x 256.
// ---------------------------------------------------------------------------
__global__ void k_prep(const float* __restrict__ na, const float* __restrict__ nb,
                       const float* __restrict__ We1, const float* __restrict__ be1,
                       const float* __restrict__ We2w) {
    int blk = blockIdx.x, t = threadIdx.x;
    if (blk < 128) {
        bool isA = blk < 64;
        int r0 = (isA ? blk : blk - 64) * 8;
        const float* X = isA ? na : nb;
        const float* W = We1 + (isA ? 0 : ND) * ED;
        __shared__ float xs[8][ND];
        for (int i = t; i < 8 * ND; i += 256) xs[i >> 7][i & 127] = X[(r0 + (i >> 7)) * ND + (i & 127)];
        __syncthreads();
        if (t < 128) {
            int d = t;
            float acc[8];
            float bb = isA ? be1[d] : 0.0f;
#pragma unroll
            for (int i = 0; i < 8; i++) acc[i] = bb;
#pragma unroll 4
            for (int k = 0; k < ND; k++) {
                float w = W[k * ED + d];
#pragma unroll
                for (int i = 0; i < 8; i++) acc[i] = fmaf(xs[i][k], w, acc[i]);
            }
            float* dst = isA ? g_A1 : g_B1;
#pragma unroll
            for (int i = 0; i < 8; i++) dst[(r0 + i) * ED + d] = acc[i];
        }
    } else {
        // fp16 hi/lo weight images; thread handles 8 consecutive k for one n.
        int wu = (blk - 128) * 256 + t;        // 0..6143
        int region = wu >> 10;                  // 0..5
        int r = wu & 1023;
        int n = r >> 3;
        int jj = (r & 7) * 8;
        const float* src;
        char* base;
        if (region < 4) {
            src = We1 + (size_t)(2 * ND + region * 64 + jj) * ED + n;
            base = g_WeB + region * 2 * TILEB;
        } else {
            int c = region - 4;
            src = We2w + (size_t)(c * 64 + jj) * ED + n;
            base = g_We2B + c * 2 * TILEB;
        }
        float x[8];
#pragma unroll
        for (int s2 = 0; s2 < 8; s2++) x[s2] = __ldg(src + (size_t)s2 * ED);
        uint32_t hw[4], lw[4];
#pragma unroll
        for (int p = 0; p < 4; p++) {
            uint32_t hp = cvt2h(x[2 * p], x[2 * p + 1]);
            __half2 hh = *(__half2*)&hp;
            float l0 = x[2 * p]     - __low2float(hh);
            float l1 = x[2 * p + 1] - __high2float(hh);
            hw[p] = hp;
            lw[p] = cvt2h(l0, l1);
        }
        *(uint4*)(base + n * PADB + jj * 2)         = make_uint4(hw[0], hw[1], hw[2], hw[3]);
        *(uint4*)(base + TILEB + n * PADB + jj * 2) = make_uint4(lw[0], lw[1], lw[2], lw[3]);
    }
}

// ---------------------------------------------------------------------------
// E-chunk prefetch (LDG->regs) and fp16 store (regs->smem)
// ---------------------------------------------------------------------------
__device__ __forceinline__ void ldgA(float4* pf, const float* __restrict__ E,
                                     int a0, int b0, int c, int t) {
#pragma unroll
    for (int it = 0; it < 4; it++) {
        int u = t + it * 256;
        int m = u >> 3, g = u & 7;
        int a = a0 + (m >> 4), b = b0 + (m & 15);
        const float4* src = (const float4*)(E + (((size_t)(a * NB + b)) << 8) + c * 64 + g * 8);
        pf[it * 2]     = __ldg(src);
        pf[it * 2 + 1] = __ldg(src + 1);
    }
}
__device__ __forceinline__ void stsA(const float4* pf, char* A, int t) {
#pragma unroll
    for (int it = 0; it < 4; it++) {
        int u = t + it * 256;
        int m = u >> 3, g = u & 7;
        float4 v0 = pf[it * 2], v1 = pf[it * 2 + 1];
        uint32_t w0 = cvt2h(v0.x, v0.y), w1 = cvt2h(v0.z, v0.w);
        uint32_t w2 = cvt2h(v1.x, v1.y), w3 = cvt2h(v1.z, v1.w);
        *(uint4*)(A + m * PADB + g * 16) = make_uint4(w0, w1, w2, w3);
    }
}

// ---------------------------------------------------------------------------
// one 64-k chunk: A single fp16, B = hi + lo  (2 MMAs per atom)
// ---------------------------------------------------------------------------
__device__ __forceinline__ void gemm_chunk(uint32_t aA, uint32_t aBh, uint32_t aBl,
                                           float acc[2][8][4]) {
#pragma unroll
    for (int kk = 0; kk < 4; kk++) {
        uint32_t a0v[4], a1v[4];
        ldsm4(a0v, aA + kk * 32);
        ldsm4(a1v, aA + 16 * PADB + kk * 32);
#pragma unroll
        for (int jp = 0; jp < 4; jp++) {
            uint32_t bh[4], bl[4];
            ldsm4(bh, aBh + jp * 16 * PADB + kk * 32);
            ldsm4(bl, aBl + jp * 16 * PADB + kk * 32);
            mma16816(acc[0][2 * jp],     a0v, bh[0], bh[1]);
            mma16816(acc[0][2 * jp],     a0v, bl[0], bl[1]);
            mma16816(acc[0][2 * jp + 1], a0v, bh[2], bh[3]);
            mma16816(acc[0][2 * jp + 1], a0v, bl[2], bl[3]);
            mma16816(acc[1][2 * jp],     a1v, bh[0], bh[1]);
            mma16816(acc[1][2 * jp],     a1v, bl[0], bl[1]);
            mma16816(acc[1][2 * jp + 1], a1v, bh[2], bh[3]);
            mma16816(acc[1][2 * jp + 1], a1v, bl[2], bl[3]);
        }
    }
}

// ---------------------------------------------------------------------------
// k_edge
// ---------------------------------------------------------------------------
__global__ __launch_bounds__(256, 1)
void k_edge(const float* __restrict__ E, const float* __restrict__ be2,
            float* __restrict__ out) {
    extern __shared__ char sm[];
    const int t = threadIdx.x, lane = t & 31, wid = t >> 5;
    const int wm = wid >> 1, wn = wid & 1;
    const int lr = lane >> 2, lc = lane & 3;
    const int bt = blockIdx.x, at = blockIdx.y;
    const int b0 = bt * 16, a0 = at * 8;

    float* sA1 = (float*)(sm + SM_A1);
    float* sB1 = (float*)(sm + SM_B1);
    float* sbe2 = (float*)(sm + SM_BE2);
    const uint32_t smb = smem_u32(sm);

    const uint32_t aoff = (uint32_t)((wm * 32 + (lane & 15)) * PADB + (lane >> 4) * 16);
    const uint32_t boff = (uint32_t)((wn * 64 + (lane & 7) + ((lane >> 4) << 3)) * PADB
                                     + ((lane >> 3) & 1) * 16);

    // ---- prologue ----
    for (int i = t; i < 2304; i += 256)
        CP16(smb + BBUF + i * 16, g_WeB + i * 16);
    CP_COMMIT();
    for (int i = t; i < 4608; i += 256)
        CP16(smb + WE2 + i * 16, g_We2B + i * 16);
    CP_COMMIT();

    float4 pf[8];
    ldgA(pf, E, a0, b0, 0, t);
    stsA(pf, sm + ABUF, t);

    for (int i = t; i < 8 * ED; i += 256)  sA1[(i >> 7) * 132 + (i & 127)] = g_A1[(a0 + (i >> 7)) * ED + (i & 127)];
    for (int i = t; i < 16 * ED; i += 256) sB1[(i >> 7) * 132 + (i & 127)] = g_B1[(b0 + (i >> 7)) * ED + (i & 127)];
    if (t < 128) sbe2[t] = be2[t];

    CP_WAIT(1);
    __syncthreads();

    float acc[2][8][4];
#pragma unroll
    for (int i = 0; i < 2; i++)
#pragma unroll
        for (int j = 0; j < 8; j++)
#pragma unroll
            for (int q = 0; q < 4; q++) acc[i][j][q] = 0.0f;

    // ---- GEMM1: 4 k-chunks, A reg-prefetch + B cp.async double-buffer ----
#pragma unroll
    for (int c = 0; c < 4; c++) {
        int s = c & 1;
        if (c < 3) {
            ldgA(pf, E, a0, b0, c + 1, t);
            uint32_t dst = smb + BBUF + (s ^ 1) * 2 * TILEB;
            const char* src = g_WeB + (c + 1) * 2 * TILEB;
            for (int i = t; i < 2304; i += 256)
                CP16(dst + i * 16, src + i * 16);
            CP_COMMIT();
        }
        uint32_t bb = smb + BBUF + s * 2 * TILEB;
        gemm_chunk(smb + ABUF + aoff, bb + boff, bb + TILEB + boff, acc);
        __syncthreads();
        if (c < 3) {
            stsA(pf, sm + ABUF, t);
            CP_WAIT(0);
            __syncthreads();
        }
    }

    // ---- epilogue 1: h = relu(D + A1 + B1) -> fp16 image (chunk0=ABUF, chunk1=BBUF) ----
    {
        char* Hh = (wn == 0) ? (sm + ABUF) : (sm + BBUF);
#pragma unroll
        for (int i = 0; i < 2; i++) {
#pragma unroll
            for (int j = 0; j < 8; j++) {
                int m0 = wm * 32 + i * 16 + lr;
                int col = wn * 64 + j * 8 + lc * 2;
                int cc2 = (col & 63) * 2;
                float f0 = fmaxf(acc[i][j][0] + sA1[(m0 >> 4) * 132 + col]     + sB1[(m0 & 15) * 132 + col],     0.0f);
                float f1 = fmaxf(acc[i][j][1] + sA1[(m0 >> 4) * 132 + col + 1] + sB1[(m0 & 15) * 132 + col + 1], 0.0f);
                *(uint32_t*)(Hh + m0 * PADB + cc2) = cvt2h(f0, f1);
                int m1 = m0 + 8;
                f0 = fmaxf(acc[i][j][2] + sA1[(m1 >> 4) * 132 + col]     + sB1[(m1 & 15) * 132 + col],     0.0f);
                f1 = fmaxf(acc[i][j][3] + sA1[(m1 >> 4) * 132 + col + 1] + sB1[(m1 & 15) * 132 + col + 1], 0.0f);
                *(uint32_t*)(Hh + m1 * PADB + cc2) = cvt2h(f0, f1);
            }
        }
    }
    __syncthreads();

    // ---- GEMM2: h @ We2, 2 k-chunks ----
#pragma unroll
    for (int i = 0; i < 2; i++)
#pragma unroll
        for (int j = 0; j < 8; j++)
#pragma unroll
            for (int q = 0; q < 4; q++) acc[i][j][q] = 0.0f;

#pragma unroll
    for (int c2 = 0; c2 < 2; c2++) {
        uint32_t ha = smb + ((c2 == 0) ? ABUF : BBUF);
        uint32_t wb = smb + WE2 + c2 * 2 * TILEB;
        gemm_chunk(ha + aoff, wb + boff, wb + TILEB + boff, acc);
    }
    __syncthreads();

    // ---- epilogue 2: L = relu(D + be2) -> sL ----
    float* sL = (float*)(sm + ABUF);
#pragma unroll
    for (int i = 0; i < 2; i++) {
#pragma unroll
        for (int j = 0; j < 8; j++) {
            int m0 = wm * 32 + i * 16 + lr;
            int col = wn * 64 + j * 8 + lc * 2;
            sL[m0 * 132 + col]     = fmaxf(acc[i][j][0] + sbe2[col],     0.0f);
            sL[m0 * 132 + col + 1] = fmaxf(acc[i][j][1] + sbe2[col + 1], 0.0f);
            int m1 = m0 + 8;
            sL[m1 * 132 + col]     = fmaxf(acc[i][j][2] + sbe2[col],     0.0f);
            sL[m1 * 132 + col + 1] = fmaxf(acc[i][j][3] + sbe2[col + 1], 0.0f);
        }
    }
    __syncthreads();

    // ---- coalesced out writes ----
    for (int i = t; i < 4096; i += 256) {
        int m = i >> 5;
        int cg = (i & 31) * 4;
        int ga = a0 + (m >> 4), gb = b0 + (m & 15);
        *(float4*)&out[((size_t)(ga * NB + gb)) * ED + cg] = *(float4*)&sL[m * 132 + cg];
    }

    // ---- deterministic partial reductions (conflict-free streaming stores) ----
    for (int q = t; q < 8 * ED; q += 256) {
        int la2 = q >> 7, n = q & 127;
        float s = 0.0f;
#pragma unroll
        for (int lb2 = 0; lb2 < 16; lb2++) s += sL[(la2 * 16 + lb2) * 132 + n];
        g_sumA_part[((size_t)(a0 + la2) * 32 + bt) * ED + n] = s;
    }
    for (int q = t; q < 16 * ED; q += 256) {
        int lb2 = q >> 7, n = q & 127;
        float s = 0.0f;
#pragma unroll
        for (int la2 = 0; la2 < 8; la2++) s += sL[(la2 * 16 + lb2) * 132 + n];
        g_sumB_part[((size_t)(b0 + lb2) * 64 + at) * ED + n] = s;
    }
}

// ---------------------------------------------------------------------------
// k_node: reduce partials (4-way ILP) + node MLPs.
// ---------------------------------------------------------------------------
__global__ void k_node(const float* __restrict__ na, const float* __restrict__ nb,
                       const float* __restrict__ Wn1, const float* __restrict__ bn1,
                       const float* __restrict__ Wn2, const float* __restrict__ bn2,
                       float* __restrict__ out) {
    int r = blockIdx.x;
    int d = threadIdx.x;
    bool isA = (r < NA);
    int rr = isA ? r : r - NA;
    __shared__ float xs[2 * ND];
    __shared__ float h1[ND];
    xs[d] = (isA ? na : nb)[rr * ND + d];
    float s0 = 0.f, s1 = 0.f, s2 = 0.f, s3 = 0.f;
    if (isA) {
        const float* p = g_sumA_part + (size_t)rr * 32 * ED + d;
#pragma unroll
        for (int tt = 0; tt < 32; tt += 4) {
            s0 += __ldg(p + (size_t)(tt + 0) * ED);
            s1 += __ldg(p + (size_t)(tt + 1) * ED);
            s2 += __ldg(p + (size_t)(tt + 2) * ED);
            s3 += __ldg(p + (size_t)(tt + 3) * ED);
        }
    } else {
        const float* p = g_sumB_part + (size_t)rr * 64 * ED + d;
#pragma unroll
        for (int tt = 0; tt < 64; tt += 4) {
            s0 += __ldg(p + (size_t)(tt + 0) * ED);
            s1 += __ldg(p + (size_t)(tt + 1) * ED);
            s2 += __ldg(p + (size_t)(tt + 2) * ED);
            s3 += __ldg(p + (size_t)(tt + 3) * ED);
        }
    }
    xs[ND + d] = (s0 + s1) + (s2 + s3);
    __syncthreads();
    float acc = bn1[d];
#pragma unroll 8
    for (int k = 0; k < 2 * ND; k++) acc = fmaf(xs[k], Wn1[k * ND + d], acc);
    h1[d] = fmaxf(acc, 0.0f);
    __syncthreads();
    float acc2 = bn2[d];
#pragma unroll 8
    for (int k = 0; k < ND; k++) acc2 = fmaf(h1[k], Wn2[k * ND + d], acc2);
    size_t off = (size_t)NA * NB * ED + (isA ? 0 : (size_t)NA * ND) + (size_t)rr * ND + d;
    out[off] = fmaxf(acc2, 0.0f);
}

// ---------------------------------------------------------------------------
extern "C" void kernel_launch(void* const* d_in, const int* in_sizes, int n_in,
                              void* d_out, int out_size) {
    const float* edge = (const float*)d_in[0];
    const float* na   = (const float*)d_in[1];
    const float* nb   = (const float*)d_in[2];
    const float* We1  = (const float*)d_in[3];
    const float* be1  = (const float*)d_in[4];
    const float* We2  = (const float*)d_in[5];
    const float* be2  = (const float*)d_in[6];
    const float* Wn1  = (const float*)d_in[7];
    const float* bn1  = (const float*)d_in[8];
    const float* Wn2  = (const float*)d_in[9];
    const float* bn2  = (const float*)d_in[10];
    float* out = (float*)d_out;

    k_prep<<<152, 256>>>(na, nb, We1, be1, We2);

    static int smem_set = 0;
    if (!smem_set) {
        cudaFuncSetAttribute(k_edge, cudaFuncAttributeMaxDynamicSharedMemorySize, SM_TOTAL);
        smem_set = 1;
    }
    dim3 grid(NB / 16, NA / 8);
    k_edge<<<grid, 256, SM_TOTAL>>>(edge, be2, out);

    k_node<<<NA + NB, 128>>>(na, nb, Wn1, bn1, Wn2, bn2, out);
}

// round 12
// speedup vs baseline: 1.8493x; 1.3960x over previous
#include <cuda_runtime.h>
#include <cuda_fp16.h>
#include <cstdint>

#define NA 512
#define NB 512
#define ND 128
#define ED 128

#define PADB 144
#define TILEB 18432        // 128 * 144

// ---------------- device scratch ----------------
__device__ float g_A1[NA * ED];
__device__ float g_B1[NB * ED];
__device__ float g_sumA_part[(size_t)NA * 32 * ED];   // [a][b_tile(32)][d]
__device__ float g_sumB_part[(size_t)NB * 64 * ED];   // [b][a_tile(64)][d]
__device__ __align__(16) char g_WeB[4 * TILEB];        // We^T  4 chunks (fp16)
__device__ __align__(16) char g_We2B[2 * TILEB];       // We2^T 2 chunks (fp16)

// ---------------- helpers ----------------
__device__ __forceinline__ uint32_t smem_u32(const void* p) {
    uint32_t a;
    asm("{ .reg .u64 t; cvta.to.shared.u64 t, %1; cvt.u32.u64 %0, t; }" : "=r"(a) : "l"(p));
    return a;
}
__device__ __forceinline__ uint32_t cvt2h(float f0, float f1) {
    uint32_t r;
    asm("cvt.rn.f16x2.f32 %0, %1, %2;" : "=r"(r) : "f"(f1), "f"(f0));  // low half = f0
    return r;
}
__device__ __forceinline__ void mma16816(float* c, const uint32_t* a, uint32_t b0, uint32_t b1) {
    asm volatile(
        "mma.sync.aligned.m16n8k16.row.col.f32.f16.f16.f32 "
        "{%0,%1,%2,%3}, {%4,%5,%6,%7}, {%8,%9}, {%0,%1,%2,%3};"
        : "+f"(c[0]), "+f"(c[1]), "+f"(c[2]), "+f"(c[3])
        : "r"(a[0]), "r"(a[1]), "r"(a[2]), "r"(a[3]), "r"(b0), "r"(b1));
}
__device__ __forceinline__ void ldsm4(uint32_t* r, uint32_t addr) {
    asm volatile("ldmatrix.sync.aligned.m8n8.x4.shared.b16 {%0,%1,%2,%3}, [%4];"
                 : "=r"(r[0]), "=r"(r[1]), "=r"(r[2]), "=r"(r[3]) : "r"(addr));
}
#define CP16(dst, src) asm volatile("cp.async.cg.shared.global [%0], [%1], 16;" :: "r"(dst), "l"(src))
#define CP_COMMIT()    asm volatile("cp.async.commit_group;" ::: "memory")
#define CP_WAIT(n)     asm volatile("cp.async.wait_group %0;" :: "n"(n) : "memory")

// ---------------- SMEM layout (bytes) ----------------
#define ABUF    0                       // TILEB : A fp16 chunk; then h chunk0
#define BBUF    18432                   // 2 stages x TILEB = 36864 ; stage0 reused for h chunk1
#define WE2     55296                   // 2*TILEB = 36864
#define SM_A1   92160                   // 8*132*4  = 4224
#define SM_B1   96384                   // 16*132*4 = 8448
#define SM_BE2  104832                  // 512
#define SM_TOTAL 105344
// sL overlay at ABUF: 128*132*4 = 67584 (spans into WE2; all dead after GEMM2)

// ---------------------------------------------------------------------------
// k_prep: node pre-GEMMs (256 blocks x 4 rows) + fp16 weight images (24 blocks).
// ---------------------------------------------------------------------------
__global__ void k_prep(const float* __restrict__ na, const float* __restrict__ nb,
                       const float* __restrict__ We1, const float* __restrict__ be1,
                       const float* __restrict__ We2w) {
    int blk = blockIdx.x, t = threadIdx.x;
    if (blk < 256) {
        bool isA = blk < 128;
        int r0 = (isA ? blk : blk - 128) * 4;
        const float* X = isA ? na : nb;
        const float* W = We1 + (isA ? 0 : ND) * ED;
        __shared__ float xs[4][ND];
        for (int i = t; i < 4 * ND; i += 256) xs[i >> 7][i & 127] = X[(r0 + (i >> 7)) * ND + (i & 127)];
        __syncthreads();
        int d = t & 127, half = t >> 7;      // half: rows {2*half, 2*half+1}
        float acc0, acc1;
        acc0 = acc1 = isA ? be1[d] : 0.0f;
#pragma unroll 4
        for (int k = 0; k < ND; k++) {
            float w = W[k * ED + d];
            acc0 = fmaf(xs[2 * half][k], w, acc0);
            acc1 = fmaf(xs[2 * half + 1][k], w, acc1);
        }
        float* dst = isA ? g_A1 : g_B1;
        dst[(r0 + 2 * half) * ED + d] = acc0;
        dst[(r0 + 2 * half + 1) * ED + d] = acc1;
    } else {
        // fp16 weight images; thread handles 8 consecutive k for one n.
        int wu = (blk - 256) * 256 + t;        // 0..6143
        int region = wu >> 10;                  // 0..5
        int r = wu & 1023;
        int n = r >> 3;
        int jj = (r & 7) * 8;
        const float* src;
        char* base;
        if (region < 4) {
            src = We1 + (size_t)(2 * ND + region * 64 + jj) * ED + n;
            base = g_WeB + region * TILEB;
        } else {
            int c = region - 4;
            src = We2w + (size_t)(c * 64 + jj) * ED + n;
            base = g_We2B + c * TILEB;
        }
        float x[8];
#pragma unroll
        for (int s2 = 0; s2 < 8; s2++) x[s2] = __ldg(src + (size_t)s2 * ED);
        uint32_t hw[4];
#pragma unroll
        for (int p = 0; p < 4; p++) hw[p] = cvt2h(x[2 * p], x[2 * p + 1]);
        *(uint4*)(base + n * PADB + jj * 2) = make_uint4(hw[0], hw[1], hw[2], hw[3]);
    }
}

// ---------------------------------------------------------------------------
// E chunk: LDG -> fp16 -> smem (direct; occ-2 hides latency)
// ---------------------------------------------------------------------------
__device__ __forceinline__ void loadA(const float* __restrict__ E, int a0, int b0,
                                      int c, char* A, int t) {
#pragma unroll
    for (int it = 0; it < 4; it++) {
        int u = t + it * 256;
        int m = u >> 3, g = u & 7;
        int a = a0 + (m >> 4), b = b0 + (m & 15);
        const float4* src = (const float4*)(E + (((size_t)(a * NB + b)) << 8) + c * 64 + g * 8);
        float4 v0 = __ldg(src);
        float4 v1 = __ldg(src + 1);
        uint32_t w0 = cvt2h(v0.x, v0.y), w1 = cvt2h(v0.z, v0.w);
        uint32_t w2 = cvt2h(v1.x, v1.y), w3 = cvt2h(v1.z, v1.w);
        *(uint4*)(A + m * PADB + g * 16) = make_uint4(w0, w1, w2, w3);
    }
}

// ---------------------------------------------------------------------------
// one 64-k chunk, single fp16 MMA per atom
// ---------------------------------------------------------------------------
__device__ __forceinline__ void gemm_chunk(uint32_t aA, uint32_t aB, float acc[2][8][4]) {
#pragma unroll
    for (int kk = 0; kk < 4; kk++) {
        uint32_t a0v[4], a1v[4];
        ldsm4(a0v, aA + kk * 32);
        ldsm4(a1v, aA + 16 * PADB + kk * 32);
#pragma unroll
        for (int jp = 0; jp < 4; jp++) {
            uint32_t bv[4];
            ldsm4(bv, aB + jp * 16 * PADB + kk * 32);
            mma16816(acc[0][2 * jp],     a0v, bv[0], bv[1]);
            mma16816(acc[0][2 * jp + 1], a0v, bv[2], bv[3]);
            mma16816(acc[1][2 * jp],     a1v, bv[0], bv[1]);
            mma16816(acc[1][2 * jp + 1], a1v, bv[2], bv[3]);
        }
    }
}

// ---------------------------------------------------------------------------
// k_edge: occupancy 2
// ---------------------------------------------------------------------------
__global__ __launch_bounds__(256, 2)
void k_edge(const float* __restrict__ E, const float* __restrict__ be2,
            float* __restrict__ out) {
    extern __shared__ char sm[];
    const int t = threadIdx.x, lane = t & 31, wid = t >> 5;
    const int wm = wid >> 1, wn = wid & 1;
    const int lr = lane >> 2, lc = lane & 3;
    const int bt = blockIdx.x, at = blockIdx.y;
    const int b0 = bt * 16, a0 = at * 8;

    float* sA1 = (float*)(sm + SM_A1);
    float* sB1 = (float*)(sm + SM_B1);
    float* sbe2 = (float*)(sm + SM_BE2);
    const uint32_t smb = smem_u32(sm);

    const uint32_t aoff = (uint32_t)((wm * 32 + (lane & 15)) * PADB + (lane >> 4) * 16);
    const uint32_t boff = (uint32_t)((wn * 64 + (lane & 7) + ((lane >> 4) << 3)) * PADB
                                     + ((lane >> 3) & 1) * 16);

    // ---- prologue: B0 + We2 cp.async, E chunk0, A1/B1/be2 staging ----
    for (int i = t; i < 1152; i += 256)
        CP16(smb + BBUF + i * 16, g_WeB + i * 16);
    CP_COMMIT();
    for (int i = t; i < 2304; i += 256)
        CP16(smb + WE2 + i * 16, g_We2B + i * 16);
    CP_COMMIT();

    loadA(E, a0, b0, 0, sm + ABUF, t);

    for (int i = t; i < 8 * ED; i += 256)  sA1[(i >> 7) * 132 + (i & 127)] = g_A1[(a0 + (i >> 7)) * ED + (i & 127)];
    for (int i = t; i < 16 * ED; i += 256) sB1[(i >> 7) * 132 + (i & 127)] = g_B1[(b0 + (i >> 7)) * ED + (i & 127)];
    if (t < 128) sbe2[t] = be2[t];

    CP_WAIT(1);
    __syncthreads();

    float acc[2][8][4];
#pragma unroll
    for (int i = 0; i < 2; i++)
#pragma unroll
        for (int j = 0; j < 8; j++)
#pragma unroll
            for (int q = 0; q < 4; q++) acc[i][j][q] = 0.0f;

    // ---- GEMM1: 4 k-chunks, B cp.async double-buffered, A single-buffered ----
#pragma unroll
    for (int c = 0; c < 4; c++) {
        int s = c & 1;
        if (c < 3) {
            uint32_t dst = smb + BBUF + (s ^ 1) * TILEB;
            const char* src = g_WeB + (c + 1) * TILEB;
            for (int i = t; i < 1152; i += 256)
                CP16(dst + i * 16, src + i * 16);
            CP_COMMIT();
        }
        gemm_chunk(smb + ABUF + aoff, smb + BBUF + s * TILEB + boff, acc);
        __syncthreads();
        if (c < 3) {
            loadA(E, a0, b0, c + 1, sm + ABUF, t);
            CP_WAIT(0);
            __syncthreads();
        }
    }

    // ---- epilogue 1: h = relu(D + A1 + B1) -> fp16 (chunk0=ABUF, chunk1=BBUF) ----
    {
        char* Hh = (wn == 0) ? (sm + ABUF) : (sm + BBUF);
#pragma unroll
        for (int i = 0; i < 2; i++) {
#pragma unroll
            for (int j = 0; j < 8; j++) {
                int m0 = wm * 32 + i * 16 + lr;
                int col = wn * 64 + j * 8 + lc * 2;
                int cc2 = (col & 63) * 2;
                float f0 = fmaxf(acc[i][j][0] + sA1[(m0 >> 4) * 132 + col]     + sB1[(m0 & 15) * 132 + col],     0.0f);
                float f1 = fmaxf(acc[i][j][1] + sA1[(m0 >> 4) * 132 + col + 1] + sB1[(m0 & 15) * 132 + col + 1], 0.0f);
                *(uint32_t*)(Hh + m0 * PADB + cc2) = cvt2h(f0, f1);
                int m1 = m0 + 8;
                f0 = fmaxf(acc[i][j][2] + sA1[(m1 >> 4) * 132 + col]     + sB1[(m1 & 15) * 132 + col],     0.0f);
                f1 = fmaxf(acc[i][j][3] + sA1[(m1 >> 4) * 132 + col + 1] + sB1[(m1 & 15) * 132 + col + 1], 0.0f);
                *(uint32_t*)(Hh + m1 * PADB + cc2) = cvt2h(f0, f1);
            }
        }
    }
    __syncthreads();

    // ---- GEMM2: h @ We2, 2 k-chunks ----
#pragma unroll
    for (int i = 0; i < 2; i++)
#pragma unroll
        for (int j = 0; j < 8; j++)
#pragma unroll
            for (int q = 0; q < 4; q++) acc[i][j][q] = 0.0f;

#pragma unroll
    for (int c2 = 0; c2 < 2; c2++) {
        uint32_t ha = smb + ((c2 == 0) ? ABUF : BBUF);
        gemm_chunk(ha + aoff, smb + WE2 + c2 * TILEB + boff, acc);
    }
    __syncthreads();

    // ---- epilogue 2: L = relu(D + be2) -> sL ----
    float* sL = (float*)(sm + ABUF);
#pragma unroll
    for (int i = 0; i < 2; i++) {
#pragma unroll
        for (int j = 0; j < 8; j++) {
            int m0 = wm * 32 + i * 16 + lr;
            int col = wn * 64 + j * 8 + lc * 2;
            sL[m0 * 132 + col]     = fmaxf(acc[i][j][0] + sbe2[col],     0.0f);
            sL[m0 * 132 + col + 1] = fmaxf(acc[i][j][1] + sbe2[col + 1], 0.0f);
            int m1 = m0 + 8;
            sL[m1 * 132 + col]     = fmaxf(acc[i][j][2] + sbe2[col],     0.0f);
            sL[m1 * 132 + col + 1] = fmaxf(acc[i][j][3] + sbe2[col + 1], 0.0f);
        }
    }
    __syncthreads();

    // ---- coalesced out writes ----
    for (int i = t; i < 4096; i += 256) {
        int m = i >> 5;
        int cg = (i & 31) * 4;
        int ga = a0 + (m >> 4), gb = b0 + (m & 15);
        *(float4*)&out[((size_t)(ga * NB + gb)) * ED + cg] = *(float4*)&sL[m * 132 + cg];
    }

    // ---- deterministic partial reductions (conflict-free streaming stores) ----
    for (int q = t; q < 8 * ED; q += 256) {
        int la2 = q >> 7, n = q & 127;
        float s = 0.0f;
#pragma unroll
        for (int lb2 = 0; lb2 < 16; lb2++) s += sL[(la2 * 16 + lb2) * 132 + n];
        g_sumA_part[((size_t)(a0 + la2) * 32 + bt) * ED + n] = s;
    }
    for (int q = t; q < 16 * ED; q += 256) {
        int lb2 = q >> 7, n = q & 127;
        float s = 0.0f;
#pragma unroll
        for (int la2 = 0; la2 < 8; la2++) s += sL[(la2 * 16 + lb2) * 132 + n];
        g_sumB_part[((size_t)(b0 + lb2) * 64 + at) * ED + n] = s;
    }
}

// ---------------------------------------------------------------------------
// k_node: reduce partials (4-way ILP) + node MLPs.
// ---------------------------------------------------------------------------
__global__ void k_node(const float* __restrict__ na, const float* __restrict__ nb,
                       const float* __restrict__ Wn1, const float* __restrict__ bn1,
                       const float* __restrict__ Wn2, const float* __restrict__ bn2,
                       float* __restrict__ out) {
    int r = blockIdx.x;
    int d = threadIdx.x;
    bool isA = (r < NA);
    int rr = isA ? r : r - NA;
    __shared__ float xs[2 * ND];
    __shared__ float h1[ND];
    xs[d] = (isA ? na : nb)[rr * ND + d];
    float s0 = 0.f, s1 = 0.f, s2 = 0.f, s3 = 0.f;
    if (isA) {
        const float* p = g_sumA_part + (size_t)rr * 32 * ED + d;
#pragma unroll
        for (int tt = 0; tt < 32; tt += 4) {
            s0 += __ldg(p + (size_t)(tt + 0) * ED);
            s1 += __ldg(p + (size_t)(tt + 1) * ED);
            s2 += __ldg(p + (size_t)(tt + 2) * ED);
            s3 += __ldg(p + (size_t)(tt + 3) * ED);
        }
    } else {
        const float* p = g_sumB_part + (size_t)rr * 64 * ED + d;
#pragma unroll
        for (int tt = 0; tt < 64; tt += 4) {
            s0 += __ldg(p + (size_t)(tt + 0) * ED);
            s1 += __ldg(p + (size_t)(tt + 1) * ED);
            s2 += __ldg(p + (size_t)(tt + 2) * ED);
            s3 += __ldg(p + (size_t)(tt + 3) * ED);
        }
    }
    xs[ND + d] = (s0 + s1) + (s2 + s3);
    __syncthreads();
    float acc = bn1[d];
#pragma unroll 8
    for (int k = 0; k < 2 * ND; k++) acc = fmaf(xs[k], Wn1[k * ND + d], acc);
    h1[d] = fmaxf(acc, 0.0f);
    __syncthreads();
    float acc2 = bn2[d];
#pragma unroll 8
    for (int k = 0; k < ND; k++) acc2 = fmaf(h1[k], Wn2[k * ND + d], acc2);
    size_t off = (size_t)NA * NB * ED + (isA ? 0 : (size_t)NA * ND) + (size_t)rr * ND + d;
    out[off] = fmaxf(acc2, 0.0f);
}

// ---------------------------------------------------------------------------
extern "C" void kernel_launch(void* const* d_in, const int* in_sizes, int n_in,
                              void* d_out, int out_size) {
    const float* edge = (const float*)d_in[0];
    const float* na   = (const float*)d_in[1];
    const float* nb   = (const float*)d_in[2];
    const float* We1  = (const float*)d_in[3];
    const float* be1  = (const float*)d_in[4];
    const float* We2  = (const float*)d_in[5];
    const float* be2  = (const float*)d_in[6];
    const float* Wn1  = (const float*)d_in[7];
    const float* bn1  = (const float*)d_in[8];
    const float* Wn2  = (const float*)d_in[9];
    const float* bn2  = (const float*)d_in[10];
    float* out = (float*)d_out;

    k_prep<<<280, 256>>>(na, nb, We1, be1, We2);

    static int smem_set = 0;
    if (!smem_set) {
        cudaFuncSetAttribute(k_edge, cudaFuncAttributeMaxDynamicSharedMemorySize, SM_TOTAL);
        smem_set = 1;
    }
    dim3 grid(NB / 16, NA / 8);
    k_edge<<<grid, 256, SM_TOTAL>>>(edge, be2, out);

    k_node<<<NA + NB, 128>>>(na, nb, Wn1, bn1, Wn2, bn2, out);
}

// round 13
// speedup vs baseline: 1.9263x; 1.0416x over previous
#include <cuda_runtime.h>
#include <cuda_fp16.h>
#include <cstdint>

#define NA 512
#define NB 512
#define ND 128
#define ED 128

#define PADB 144
#define TILEB 18432        // 128 * 144

// ---------------- device scratch ----------------
__device__ float g_A1[NA * ED];
__device__ float g_B1[NB * ED];
__device__ float g_sumA_part[(size_t)NA * 32 * ED];   // [a][b_tile(32)][d]
__device__ float g_sumB_part[(size_t)NB * 64 * ED];   // [b][a_tile(64)][d]
__device__ __align__(16) char g_WeB[4 * TILEB];        // We^T  4 chunks (fp16)
__device__ __align__(16) char g_We2B[2 * TILEB];       // We2^T 2 chunks (fp16)

// ---------------- helpers ----------------
__device__ __forceinline__ uint32_t smem_u32(const void* p) {
    uint32_t a;
    asm("{ .reg .u64 t; cvta.to.shared.u64 t, %1; cvt.u32.u64 %0, t; }" : "=r"(a) : "l"(p));
    return a;
}
__device__ __forceinline__ uint32_t cvt2h(float f0, float f1) {
    uint32_t r;
    asm("cvt.rn.f16x2.f32 %0, %1, %2;" : "=r"(r) : "f"(f1), "f"(f0));  // low half = f0
    return r;
}
__device__ __forceinline__ void mma16816(float* c, const uint32_t* a, uint32_t b0, uint32_t b1) {
    asm volatile(
        "mma.sync.aligned.m16n8k16.row.col.f32.f16.f16.f32 "
        "{%0,%1,%2,%3}, {%4,%5,%6,%7}, {%8,%9}, {%0,%1,%2,%3};"
        : "+f"(c[0]), "+f"(c[1]), "+f"(c[2]), "+f"(c[3])
        : "r"(a[0]), "r"(a[1]), "r"(a[2]), "r"(a[3]), "r"(b0), "r"(b1));
}
__device__ __forceinline__ void ldsm4(uint32_t* r, uint32_t addr) {
    asm volatile("ldmatrix.sync.aligned.m8n8.x4.shared.b16 {%0,%1,%2,%3}, [%4];"
                 : "=r"(r[0]), "=r"(r[1]), "=r"(r[2]), "=r"(r[3]) : "r"(addr));
}
#define CP16(dst, src) asm volatile("cp.async.cg.shared.global [%0], [%1], 16;" :: "r"(dst), "l"(src))
#define CP_COMMIT()    asm volatile("cp.async.commit_group;" ::: "memory")
#define CP_WAIT(n)     asm volatile("cp.async.wait_group %0;" :: "n"(n) : "memory")

// ---------------- SMEM layout (bytes) ----------------
#define ABUF    0                       // TILEB : A fp16 chunk; then h chunk0
#define BBUF    18432                   // 2 stages x TILEB = 36864 ; stage0 reused for h chunk1
#define WE2     55296                   // 2*TILEB = 36864
#define SM_A1   92160                   // 8*132*4  = 4224
#define SM_B1   96384                   // 16*132*4 = 8448
#define SM_BE2  104832                  // 512
#define SM_TOTAL 105344
// sumB partial buffer overlays ABUF after GEMM2: [4][2][16][33] float2 = 33792 B

// ---------------------------------------------------------------------------
// k_prep: node pre-GEMMs (256 blocks x 4 rows, MLP16) + fp16 weight images.
// ---------------------------------------------------------------------------
__global__ void k_prep(const float* __restrict__ na, const float* __restrict__ nb,
                       const float* __restrict__ We1, const float* __restrict__ be1,
                       const float* __restrict__ We2w) {
    int blk = blockIdx.x, t = threadIdx.x;
    if (blk < 256) {
        bool isA = blk < 128;
        int r0 = (isA ? blk : blk - 128) * 4;
        const float* X = isA ? na : nb;
        const float* W = We1 + (isA ? 0 : ND) * ED;
        __shared__ float xs[4][ND];
        for (int i = t; i < 4 * ND; i += 256) xs[i >> 7][i & 127] = X[(r0 + (i >> 7)) * ND + (i & 127)];
        __syncthreads();
        int d = t & 127, half = t >> 7;
        float acc0, acc1;
        acc0 = acc1 = isA ? be1[d] : 0.0f;
        for (int k0 = 0; k0 < ND; k0 += 16) {
            float w[16];
#pragma unroll
            for (int u = 0; u < 16; u++) w[u] = __ldg(&W[(k0 + u) * ED + d]);
#pragma unroll
            for (int u = 0; u < 16; u++) {
                acc0 = fmaf(xs[2 * half][k0 + u], w[u], acc0);
                acc1 = fmaf(xs[2 * half + 1][k0 + u], w[u], acc1);
            }
        }
        float* dst = isA ? g_A1 : g_B1;
        dst[(r0 + 2 * half) * ED + d] = acc0;
        dst[(r0 + 2 * half + 1) * ED + d] = acc1;
    } else {
        // fp16 weight images; thread handles 8 consecutive k for one n.
        int wu = (blk - 256) * 256 + t;        // 0..6143
        int region = wu >> 10;                  // 0..5
        int r = wu & 1023;
        int n = r >> 3;
        int jj = (r & 7) * 8;
        const float* src;
        char* base;
        if (region < 4) {
            src = We1 + (size_t)(2 * ND + region * 64 + jj) * ED + n;
            base = g_WeB + region * TILEB;
        } else {
            int c = region - 4;
            src = We2w + (size_t)(c * 64 + jj) * ED + n;
            base = g_We2B + c * TILEB;
        }
        float x[8];
#pragma unroll
        for (int s2 = 0; s2 < 8; s2++) x[s2] = __ldg(src + (size_t)s2 * ED);
        uint32_t hw[4];
#pragma unroll
        for (int p = 0; p < 4; p++) hw[p] = cvt2h(x[2 * p], x[2 * p + 1]);
        *(uint4*)(base + n * PADB + jj * 2) = make_uint4(hw[0], hw[1], hw[2], hw[3]);
    }
}

// ---------------------------------------------------------------------------
// E chunk: LDG -> fp16 -> smem
// ---------------------------------------------------------------------------
__device__ __forceinline__ void loadA(const float* __restrict__ E, int a0, int b0,
                                      int c, char* A, int t) {
#pragma unroll
    for (int it = 0; it < 4; it++) {
        int u = t + it * 256;
        int m = u >> 3, g = u & 7;
        int a = a0 + (m >> 4), b = b0 + (m & 15);
        const float4* src = (const float4*)(E + (((size_t)(a * NB + b)) << 8) + c * 64 + g * 8);
        float4 v0 = __ldg(src);
        float4 v1 = __ldg(src + 1);
        uint32_t w0 = cvt2h(v0.x, v0.y), w1 = cvt2h(v0.z, v0.w);
        uint32_t w2 = cvt2h(v1.x, v1.y), w3 = cvt2h(v1.z, v1.w);
        *(uint4*)(A + m * PADB + g * 16) = make_uint4(w0, w1, w2, w3);
    }
}

// ---------------------------------------------------------------------------
// one 64-k chunk, single fp16 MMA per atom
// ---------------------------------------------------------------------------
__device__ __forceinline__ void gemm_chunk(uint32_t aA, uint32_t aB, float acc[2][8][4]) {
#pragma unroll
    for (int kk = 0; kk < 4; kk++) {
        uint32_t a0v[4], a1v[4];
        ldsm4(a0v, aA + kk * 32);
        ldsm4(a1v, aA + 16 * PADB + kk * 32);
#pragma unroll
        for (int jp = 0; jp < 4; jp++) {
            uint32_t bv[4];
            ldsm4(bv, aB + jp * 16 * PADB + kk * 32);
            mma16816(acc[0][2 * jp],     a0v, bv[0], bv[1]);
            mma16816(acc[0][2 * jp + 1], a0v, bv[2], bv[3]);
            mma16816(acc[1][2 * jp],     a1v, bv[0], bv[1]);
            mma16816(acc[1][2 * jp + 1], a1v, bv[2], bv[3]);
        }
    }
}

// ---------------------------------------------------------------------------
// k_edge: occupancy 2, register-resident epilogue-2
// ---------------------------------------------------------------------------
__global__ __launch_bounds__(256, 2)
void k_edge(const float* __restrict__ E, const float* __restrict__ be2,
            float* __restrict__ out) {
    extern __shared__ char sm[];
    const int t = threadIdx.x, lane = t & 31, wid = t >> 5;
    const int wm = wid >> 1, wn = wid & 1;
    const int lr = lane >> 2, lc = lane & 3;
    const int bt = blockIdx.x, at = blockIdx.y;
    const int b0 = bt * 16, a0 = at * 8;

    float* sA1 = (float*)(sm + SM_A1);
    float* sB1 = (float*)(sm + SM_B1);
    float* sbe2 = (float*)(sm + SM_BE2);
    const uint32_t smb = smem_u32(sm);

    const uint32_t aoff = (uint32_t)((wm * 32 + (lane & 15)) * PADB + (lane >> 4) * 16);
    const uint32_t boff = (uint32_t)((wn * 64 + (lane & 7) + ((lane >> 4) << 3)) * PADB
                                     + ((lane >> 3) & 1) * 16);

    // ---- prologue ----
    for (int i = t; i < 1152; i += 256)
        CP16(smb + BBUF + i * 16, g_WeB + i * 16);
    CP_COMMIT();
    for (int i = t; i < 2304; i += 256)
        CP16(smb + WE2 + i * 16, g_We2B + i * 16);
    CP_COMMIT();

    loadA(E, a0, b0, 0, sm + ABUF, t);

    for (int i = t; i < 8 * ED; i += 256)  sA1[(i >> 7) * 132 + (i & 127)] = g_A1[(a0 + (i >> 7)) * ED + (i & 127)];
    for (int i = t; i < 16 * ED; i += 256) sB1[(i >> 7) * 132 + (i & 127)] = g_B1[(b0 + (i >> 7)) * ED + (i & 127)];
    if (t < 128) sbe2[t] = be2[t];

    CP_WAIT(1);
    __syncthreads();

    float acc[2][8][4];
#pragma unroll
    for (int i = 0; i < 2; i++)
#pragma unroll
        for (int j = 0; j < 8; j++)
#pragma unroll
            for (int q = 0; q < 4; q++) acc[i][j][q] = 0.0f;

    // ---- GEMM1: 4 k-chunks ----
#pragma unroll
    for (int c = 0; c < 4; c++) {
        int s = c & 1;
        if (c < 3) {
            uint32_t dst = smb + BBUF + (s ^ 1) * TILEB;
            const char* src = g_WeB + (c + 1) * TILEB;
            for (int i = t; i < 1152; i += 256)
                CP16(dst + i * 16, src + i * 16);
            CP_COMMIT();
        }
        gemm_chunk(smb + ABUF + aoff, smb + BBUF + s * TILEB + boff, acc);
        __syncthreads();
        if (c < 3) {
            loadA(E, a0, b0, c + 1, sm + ABUF, t);
            CP_WAIT(0);
            __syncthreads();
        }
    }

    // ---- epilogue 1: h = relu(D + A1 + B1) -> fp16 (chunk0=ABUF, chunk1=BBUF) ----
    {
        char* Hh = (wn == 0) ? (sm + ABUF) : (sm + BBUF);
#pragma unroll
        for (int i = 0; i < 2; i++) {
#pragma unroll
            for (int j = 0; j < 8; j++) {
                int m0 = wm * 32 + i * 16 + lr;
                int col = wn * 64 + j * 8 + lc * 2;
                int cc2 = (col & 63) * 2;
                float f0 = fmaxf(acc[i][j][0] + sA1[(m0 >> 4) * 132 + col]     + sB1[(m0 & 15) * 132 + col],     0.0f);
                float f1 = fmaxf(acc[i][j][1] + sA1[(m0 >> 4) * 132 + col + 1] + sB1[(m0 & 15) * 132 + col + 1], 0.0f);
                *(uint32_t*)(Hh + m0 * PADB + cc2) = cvt2h(f0, f1);
                int m1 = m0 + 8;
                f0 = fmaxf(acc[i][j][2] + sA1[(m1 >> 4) * 132 + col]     + sB1[(m1 & 15) * 132 + col],     0.0f);
                f1 = fmaxf(acc[i][j][3] + sA1[(m1 >> 4) * 132 + col + 1] + sB1[(m1 & 15) * 132 + col + 1], 0.0f);
                *(uint32_t*)(Hh + m1 * PADB + cc2) = cvt2h(f0, f1);
            }
        }
    }
    __syncthreads();

    // ---- GEMM2: h @ We2, 2 k-chunks ----
#pragma unroll
    for (int i = 0; i < 2; i++)
#pragma unroll
        for (int j = 0; j < 8; j++)
#pragma unroll
            for (int q = 0; q < 4; q++) acc[i][j][q] = 0.0f;

#pragma unroll
    for (int c2 = 0; c2 < 2; c2++) {
        uint32_t ha = smb + ((c2 == 0) ? ABUF : BBUF);
        gemm_chunk(ha + aoff, smb + WE2 + c2 * TILEB + boff, acc);
    }
    __syncthreads();   // all h/We2 smem reads done; ABUF region reusable as sumB buffer

    // ---- epilogue 2: relu+bias, direct out STG, sumA via bfly, sumB partials ----
    float2* bufB = (float2*)sm;               // [4 wm][2 wn][16 lb][33] float2
    {
        const int colBase = wn * 64;
        // out row bases: ga = a0 + wm*2 + i, gb = b0 + lr (+8)
        size_t obase0 = ((size_t)((a0 + wm * 2 + 0) * NB + b0 + lr)) * ED;
        size_t obase1 = ((size_t)((a0 + wm * 2 + 1) * NB + b0 + lr)) * ED;
#pragma unroll
        for (int j = 0; j < 8; j++) {
            int col = colBase + j * 8 + lc * 2;
            float bz0 = sbe2[col], bz1 = sbe2[col + 1];
            float2 pb0 = make_float2(0.f, 0.f), pb1 = make_float2(0.f, 0.f);
            float2 sa[2];
#pragma unroll
            for (int i = 0; i < 2; i++) {
                float v0 = fmaxf(acc[i][j][0] + bz0, 0.0f);
                float v1 = fmaxf(acc[i][j][1] + bz1, 0.0f);
                float v2 = fmaxf(acc[i][j][2] + bz0, 0.0f);
                float v3 = fmaxf(acc[i][j][3] + bz1, 0.0f);
                size_t ob = (i == 0) ? obase0 : obase1;
                *(float2*)&out[ob + col]            = make_float2(v0, v1);
                *(float2*)&out[ob + 8 * ED + col]   = make_float2(v2, v3);
                sa[i] = make_float2(v0 + v2, v1 + v3);
                pb0.x += v0; pb0.y += v1;
                pb1.x += v2; pb1.y += v3;
            }
            // sumA: reduce sa over lr (lane bits 2..4)
#pragma unroll
            for (int i = 0; i < 2; i++) {
#pragma unroll
                for (int mk = 4; mk <= 16; mk <<= 1) {
                    sa[i].x += __shfl_xor_sync(0xffffffffu, sa[i].x, mk);
                    sa[i].y += __shfl_xor_sync(0xffffffffu, sa[i].y, mk);
                }
                if (lr == j) {
                    int la = wm * 2 + i;
                    *(float2*)&g_sumA_part[((size_t)(a0 + la) * 32 + bt) * ED + col] = sa[i];
                }
            }
            // sumB partials (summed over this warp's 2 la): lb = lr and lr+8
            bufB[((wm * 2 + wn) * 16 + lr) * 33 + j * 4 + lc]       = pb0;
            bufB[((wm * 2 + wn) * 16 + lr + 8) * 33 + j * 4 + lc]   = pb1;
        }
    }
    __syncthreads();

    // ---- final sumB combine: 1024 float2 outputs over 256 threads ----
    {
        int wnf = t >> 7;                 // 0..1
        int flat = (t & 127) * 4;
#pragma unroll
        for (int u = 0; u < 4; u++) {
            int f = flat + u;             // 0..511
            int lb = f >> 5, cc = f & 31;
            float2 s = bufB[((0 * 2 + wnf) * 16 + lb) * 33 + cc];
            float2 p1 = bufB[((1 * 2 + wnf) * 16 + lb) * 33 + cc];
            float2 p2 = bufB[((2 * 2 + wnf) * 16 + lb) * 33 + cc];
            float2 p3 = bufB[((3 * 2 + wnf) * 16 + lb) * 33 + cc];
            s.x = (s.x + p1.x) + (p2.x + p3.x);
            s.y = (s.y + p1.y) + (p2.y + p3.y);
            int col = wnf * 64 + cc * 2;
            *(float2*)&g_sumB_part[((size_t)(b0 + lb) * 64 + at) * ED + col] = s;
        }
    }
}

// ---------------------------------------------------------------------------
// k_node: reduce partials (8-way ILP) + node MLPs.
// ---------------------------------------------------------------------------
__global__ void k_node(const float* __restrict__ na, const float* __restrict__ nb,
                       const float* __restrict__ Wn1, const float* __restrict__ bn1,
                       const float* __restrict__ Wn2, const float* __restrict__ bn2,
                       float* __restrict__ out) {
    int r = blockIdx.x;
    int d = threadIdx.x;
    bool isA = (r < NA);
    int rr = isA ? r : r - NA;
    __shared__ float xs[2 * ND];
    __shared__ float h1[ND];
    xs[d] = (isA ? na : nb)[rr * ND + d];
    float s[8];
#pragma unroll
    for (int u = 0; u < 8; u++) s[u] = 0.0f;
    if (isA) {
        const float* p = g_sumA_part + (size_t)rr * 32 * ED + d;
#pragma unroll
        for (int tt = 0; tt < 32; tt += 8)
#pragma unroll
            for (int u = 0; u < 8; u++) s[u] += __ldg(p + (size_t)(tt + u) * ED);
    } else {
        const float* p = g_sumB_part + (size_t)rr * 64 * ED + d;
#pragma unroll
        for (int tt = 0; tt < 64; tt += 8)
#pragma unroll
            for (int u = 0; u < 8; u++) s[u] += __ldg(p + (size_t)(tt + u) * ED);
    }
    xs[ND + d] = ((s[0] + s[1]) + (s[2] + s[3])) + ((s[4] + s[5]) + (s[6] + s[7]));
    __syncthreads();
    float acc = bn1[d];
#pragma unroll 8
    for (int k = 0; k < 2 * ND; k++) acc = fmaf(xs[k], Wn1[k * ND + d], acc);
    h1[d] = fmaxf(acc, 0.0f);
    __syncthreads();
    float acc2 = bn2[d];
#pragma unroll 8
    for (int k = 0; k < ND; k++) acc2 = fmaf(h1[k], Wn2[k * ND + d], acc2);
    size_t off = (size_t)NA * NB * ED + (isA ? 0 : (size_t)NA * ND) + (size_t)rr * ND + d;
    out[off] = fmaxf(acc2, 0.0f);
}

// ---------------------------------------------------------------------------
extern "C" void kernel_launch(void* const* d_in, const int* in_sizes, int n_in,
                              void* d_out, int out_size) {
    const float* edge = (const float*)d_in[0];
    const float* na   = (const float*)d_in[1];
    const float* nb   = (const float*)d_in[2];
    const float* We1  = (const float*)d_in[3];
    const float* be1  = (const float*)d_in[4];
    const float* We2  = (const float*)d_in[5];
    const float* be2  = (const float*)d_in[6];
    const float* Wn1  = (const float*)d_in[7];
    const float* bn1  = (const float*)d_in[8];
    const float* Wn2  = (const float*)d_in[9];
    const float* bn2  = (const float*)d_in[10];
    float* out = (float*)d_out;

    k_prep<<<280, 256>>>(na, nb, We1, be1, We2);

    static int smem_set = 0;
    if (!smem_set) {
        cudaFuncSetAttribute(k_edge, cudaFuncAttributeMaxDynamicSharedMemorySize, SM_TOTAL);
        smem_set = 1;
    }
    dim3 grid(NB / 16, NA / 8);
    k_edge<<<grid, 256, SM_TOTAL>>>(edge, be2, out);

    k_node<<<NA + NB, 128>>>(na, nb, Wn1, bn1, Wn2, bn2, out);
}